// round 1
// baseline (speedup 1.0000x reference)
#include <cuda_runtime.h>
#include <math.h>

namespace {

constexpr int T_    = 29;        // time samples per segment
constexpr int NSEG  = 3;
constexpr int B_    = 16384;
constexpr int ROWS  = NSEG * T_; // 87 output rows
constexpr int TB    = 128;       // batch elements per block
constexpr int TILE  = TB * 14;   // floats per (row, b-chunk) tile

// Advance state (r, R) by arclength s under constant curvature (ux, uy).
// Closed form of dr = R e3, dR = R skew((ux,uy,0)).
__device__ __forceinline__ void advance_state(float r[3], float R[9],
                                              float ux, float uy, float s)
{
    float w2 = fmaf(ux, ux, uy * uy);
    float w  = sqrtf(w2);
    float th = s * w;
    float b, c;
    if (th < 1e-4f) {
        // series: b = sinθ/ω ≈ s, c = (1-cosθ)/ω² ≈ s²/2  (error O(θ²) ≤ 1e-8 rel)
        b = s;
        c = 0.5f * s * s;
    } else {
        float sh, ch;
        sincosf(0.5f * th, &sh, &ch);
        b = (2.0f * sh * ch) / w;    // sinθ/ω
        c = (2.0f * sh * sh) / w2;   // (1-cosθ)/ω², cancellation-free
    }
    float ct = fmaf(-c, w2, 1.0f);   // cosθ
    float bx = b * ux, by = b * uy;
    float cx = c * ux, cy = c * uy;
    float M00 = fmaf(-cy, uy, 1.0f);
    float M01 = cx * uy;
    float M11 = fmaf(-cx, ux, 1.0f);

    // r += R * (c*uy, -c*ux, b)
    r[0] += R[0] * cy - R[1] * cx + R[2] * b;
    r[1] += R[3] * cy - R[4] * cx + R[5] * b;
    r[2] += R[6] * cy - R[7] * cx + R[8] * b;

    // R = R * M,  M = [[M00,M01,by],[M01,M11,-bx],[-by,bx,ct]]
#pragma unroll
    for (int i = 0; i < 3; i++) {
        float a0 = R[3 * i], a1 = R[3 * i + 1], a2 = R[3 * i + 2];
        R[3 * i]     = a0 * M00 + a1 * M01 - a2 * by;
        R[3 * i + 1] = a0 * M01 + a1 * M11 + a2 * bx;
        R[3 * i + 2] = a0 * by  - a1 * bx  + a2 * ct;
    }
}

__global__ void __launch_bounds__(TB) pcc_kernel(const float* __restrict__ actions,
                                                 float* __restrict__ out)
{
    __shared__ float sm[TB * 15];   // stride-15 to avoid bank conflicts
    const int tid = threadIdx.x;
    const int b   = blockIdx.x * TB + tid;
    const int row = blockIdx.y;
    const int seg = row / T_;
    const int t   = row - seg * T_;

    float a[9];
#pragma unroll
    for (int i = 0; i < 9; i++) a[i] = actions[b * 9 + i];

    float r[3] = {0.f, 0.f, 0.f};
    float R[9] = {1.f, 0.f, 0.f, 0.f, 1.f, 0.f, 0.f, 0.f, 1.f};
    float ux = 0.f, uy = 0.f;
    int len = 0;

#pragma unroll
    for (int n = 0; n < NSEG; n++) {
        if (n > seg) break;
        float l  = 0.1f + a[3 * n];            // f32, matches jnp L0 + a0
        float ld = l * 0.0075f;                // l * D
        ux = a[3 * n + 2] / (-ld);
        uy = a[3 * n + 1] / ld;
        len = (int)(l / 0.005f);               // bit-exact replication of (l/DS).astype(int32)
        if (n < seg) {
            // chain: prior segment contributes its clamped endpoint state
            advance_state(r, R, ux, uy, (float)len * 0.005f);
        }
    }
    int   tt = t < len ? t : len;              // min(row_idx, length) clamp
    advance_state(r, R, ux, uy, (float)tt * 0.005f);

    // stage state into smem, then write tile fully coalesced
#pragma unroll
    for (int k = 0; k < 3; k++) sm[tid * 15 + k] = r[k];
#pragma unroll
    for (int k = 0; k < 9; k++) sm[tid * 15 + 3 + k] = R[k];
    sm[tid * 15 + 12] = ux;
    sm[tid * 15 + 13] = uy;
    __syncthreads();

    float* obase = out + (size_t)row * ((size_t)B_ * 14) + (size_t)blockIdx.x * TILE;
#pragma unroll
    for (int i = 0; i < 14; i++) {
        int j  = tid + i * TB;        // linear index within 1792-float tile
        int bl = j / 14;
        int k  = j - bl * 14;
        obase[j] = sm[bl * 15 + k];
    }
}

} // namespace

extern "C" void kernel_launch(void* const* d_in, const int* in_sizes, int n_in,
                              void* d_out, int out_size)
{
    (void)in_sizes; (void)n_in; (void)out_size;
    const float* actions = (const float*)d_in[0];
    float* out = (float*)d_out;
    dim3 grid(B_ / TB, ROWS);
    pcc_kernel<<<grid, TB>>>(actions, out);
}

// round 2
// speedup vs baseline: 1.5777x; 1.5777x over previous
#include <cuda_runtime.h>
#include <math.h>

namespace {

constexpr int T_     = 29;        // time samples per segment
constexpr int NSEG   = 3;
constexpr int B_     = 16384;
constexpr int TB     = 128;       // batch elements per block
constexpr int TSPLIT = 2;         // t-range halves: [0,15) and [15,29)
constexpr float DS_  = 0.005f;

// Build constant-curvature transfer (M, v) for arclength s:
//   R(s) = R0*M,  r(s) = r0 + R0*v
__device__ __forceinline__ void curv_Mv(float ux, float uy, float s,
                                        float M[9], float v[3])
{
    float w2 = fmaf(ux, ux, uy * uy);
    float w  = sqrtf(w2);
    float th = s * w;
    float b, c;
    if (th < 1e-4f) {
        b = s;                    // sinθ/ω ≈ s
        c = 0.5f * s * s;         // (1-cosθ)/ω² ≈ s²/2
    } else {
        float sh, ch;
        sincosf(0.5f * th, &sh, &ch);
        b = (2.0f * sh * ch) / w;     // sinθ/ω
        c = (2.0f * sh * sh) / w2;    // (1-cosθ)/ω², cancellation-free
    }
    float ct = fmaf(-c, w2, 1.0f);    // cosθ
    float bx = b * ux, by = b * uy;
    float cx = c * ux, cy = c * uy;
    M[0] = fmaf(-cy, uy, 1.0f);  M[1] = cx * uy;              M[2] = by;
    M[3] = M[1];                 M[4] = fmaf(-cx, ux, 1.0f);  M[5] = -bx;
    M[6] = -by;                  M[7] = bx;                   M[8] = ct;
    v[0] = cy;  v[1] = -cx;  v[2] = b;
}

__device__ __forceinline__ void apply_Mv(float r[3], float R[9],
                                         const float M[9], const float v[3])
{
#pragma unroll
    for (int i = 0; i < 3; i++) {
        float a0 = R[3 * i], a1 = R[3 * i + 1], a2 = R[3 * i + 2];
        r[i] += a0 * v[0] + a1 * v[1] + a2 * v[2];
        R[3 * i]     = a0 * M[0] + a1 * M[3] + a2 * M[6];
        R[3 * i + 1] = a0 * M[1] + a1 * M[4] + a2 * M[7];
        R[3 * i + 2] = a0 * M[2] + a1 * M[5] + a2 * M[8];
    }
}

__device__ __forceinline__ void advance_state(float r[3], float R[9],
                                              float ux, float uy, float s)
{
    float M[9], v[3];
    curv_Mv(ux, uy, s, M, v);
    apply_Mv(r, R, M, v);
}

__global__ void __launch_bounds__(TB) pcc_kernel(const float* __restrict__ actions,
                                                 float* __restrict__ out)
{
    __shared__ float sm[2][TB * 14];   // double-buffered row tile (also actions stage)
    const int tid = threadIdx.x;
    const int bx  = blockIdx.x;                 // batch chunk
    const int seg = blockIdx.y / TSPLIT;
    const int tq  = blockIdx.y - seg * TSPLIT;
    const int t0  = tq == 0 ? 0  : 15;
    const int t1  = tq == 0 ? 15 : T_;
    const int b0  = bx * TB;

    // Stage this chunk's actions coalesced through smem (stride-9 reads are
    // conflict-free: gcd(9,32)=1).
#pragma unroll
    for (int i = 0; i < 9; i++)
        sm[0][tid + i * TB] = actions[(size_t)b0 * 9 + tid + i * TB];
    __syncthreads();
    float a[9];
#pragma unroll
    for (int i = 0; i < 9; i++) a[i] = sm[0][tid * 9 + i];
    __syncthreads();   // everyone done reading before buffer reuse

    // Chain through prior segments (clamped endpoints), pick up own params.
    float r[3] = {0.f, 0.f, 0.f};
    float R[9] = {1.f, 0.f, 0.f, 0.f, 1.f, 0.f, 0.f, 0.f, 1.f};
    float ux = 0.f, uy = 0.f;
    int len = 0;
#pragma unroll
    for (int n = 0; n < NSEG; n++) {
        if (n > seg) break;
        float l  = 0.1f + a[3 * n];
        float ld = l * 0.0075f;
        ux  = a[3 * n + 2] / (-ld);
        uy  = a[3 * n + 1] / ld;
        len = (int)(l / DS_);                  // replicates (l/DS).astype(int32)
        if (n < seg) advance_state(r, R, ux, uy, (float)len * DS_);
    }

    // Jump directly to this t-range's start (clamped), then march with a
    // constant per-step transfer.
    int tt0 = t0 < len ? t0 : len;
    advance_state(r, R, ux, uy, (float)tt0 * DS_);
    float Ms[9], vs[3];
    curv_Mv(ux, uy, DS_, Ms, vs);

    for (int t = t0; t < t1; ++t) {
        float* buf = sm[(t - t0) & 1];
        // pack state as 7 float2: (r0,r1)(r2,R0)(R1,R2)(R3,R4)(R5,R6)(R7,R8)(ux,uy)
        float2* pk = reinterpret_cast<float2*>(buf + tid * 14);
        pk[0] = make_float2(r[0], r[1]);
        pk[1] = make_float2(r[2], R[0]);
        pk[2] = make_float2(R[1], R[2]);
        pk[3] = make_float2(R[3], R[4]);
        pk[4] = make_float2(R[5], R[6]);
        pk[5] = make_float2(R[7], R[8]);
        pk[6] = make_float2(ux,   uy);
        __syncthreads();

        const float2* src = reinterpret_cast<const float2*>(buf);
        float2* dst = reinterpret_cast<float2*>(
            out + (size_t)(seg * T_ + t) * ((size_t)B_ * 14) + (size_t)b0 * 14);
#pragma unroll
        for (int i = 0; i < 7; i++)
            dst[tid + i * TB] = src[tid + i * TB];

        if (t < len) apply_Mv(r, R, Ms, vs);
    }
}

} // namespace

extern "C" void kernel_launch(void* const* d_in, const int* in_sizes, int n_in,
                              void* d_out, int out_size)
{
    (void)in_sizes; (void)n_in; (void)out_size;
    const float* actions = (const float*)d_in[0];
    float* out = (float*)d_out;
    dim3 grid(B_ / TB, NSEG * TSPLIT);
    pcc_kernel<<<grid, TB>>>(actions, out);
}